// round 12
// baseline (speedup 1.0000x reference)
#include <cuda_runtime.h>
#include <cuda_bf16.h>

// Scalar reduction: mean over all elements of
//   term = (a<0 && b<0) ? (b - 2a)^2 : b^2
// where a = target (d_in[1]), b = source (d_in[0]).
// Derivation: fdback - a = (a<0&&b<0) ? (b-a)-a = b-2a : (a-b)-a = -b.
//
// Single-kernel, self-resetting (graph-replay-safe) reduction with dynamic
// chunk scheduling (CHUNK=2048 float4/array, dual front-batched 8-load
// groups, one-wave grid 888=148x6). Epilogue: per-block partials written to
// an uncontended array (no serialized FP64 atomics); the ticket-elected last
// block sums the partials in parallel with all 256 threads.

__device__ double       g_fdloss_partials[1024];  // per-block partial sums
__device__ unsigned int g_fdloss_tick;            // wrapping ticket; self-resets
__device__ unsigned int g_fdloss_work;            // chunk counter; last block resets

#define CHUNK_F4 2048   // float4 per chunk per array = 32 KB/array

// one front-batched group: 4 src + 4 tgt float4 at i0 + {0,256,512,768}
__device__ __forceinline__ void fd_group(
    const float4* __restrict__ src, const float4* __restrict__ tgt, int i0,
    float& acc0, float& acc1, float& acc2, float& acc3)
{
    float4 B[4], A[4];
    #pragma unroll
    for (int k = 0; k < 4; k++) {
        B[k] = src[i0 + k * 256];
        A[k] = tgt[i0 + k * 256];
    }
    {
        float u, s;
        u = (A[0].x < 0.f && B[0].x < 0.f) ? (B[0].x - 2.f * A[0].x) : B[0].x;
        s = u * u;
        u = (A[0].y < 0.f && B[0].y < 0.f) ? (B[0].y - 2.f * A[0].y) : B[0].y;
        s += u * u;
        u = (A[0].z < 0.f && B[0].z < 0.f) ? (B[0].z - 2.f * A[0].z) : B[0].z;
        s += u * u;
        u = (A[0].w < 0.f && B[0].w < 0.f) ? (B[0].w - 2.f * A[0].w) : B[0].w;
        s += u * u;
        acc0 += s;
    }
    {
        float u, s;
        u = (A[1].x < 0.f && B[1].x < 0.f) ? (B[1].x - 2.f * A[1].x) : B[1].x;
        s = u * u;
        u = (A[1].y < 0.f && B[1].y < 0.f) ? (B[1].y - 2.f * A[1].y) : B[1].y;
        s += u * u;
        u = (A[1].z < 0.f && B[1].z < 0.f) ? (B[1].z - 2.f * A[1].z) : B[1].z;
        s += u * u;
        u = (A[1].w < 0.f && B[1].w < 0.f) ? (B[1].w - 2.f * A[1].w) : B[1].w;
        s += u * u;
        acc1 += s;
    }
    {
        float u, s;
        u = (A[2].x < 0.f && B[2].x < 0.f) ? (B[2].x - 2.f * A[2].x) : B[2].x;
        s = u * u;
        u = (A[2].y < 0.f && B[2].y < 0.f) ? (B[2].y - 2.f * A[2].y) : B[2].y;
        s += u * u;
        u = (A[2].z < 0.f && B[2].z < 0.f) ? (B[2].z - 2.f * A[2].z) : B[2].z;
        s += u * u;
        u = (A[2].w < 0.f && B[2].w < 0.f) ? (B[2].w - 2.f * A[2].w) : B[2].w;
        s += u * u;
        acc2 += s;
    }
    {
        float u, s;
        u = (A[3].x < 0.f && B[3].x < 0.f) ? (B[3].x - 2.f * A[3].x) : B[3].x;
        s = u * u;
        u = (A[3].y < 0.f && B[3].y < 0.f) ? (B[3].y - 2.f * A[3].y) : B[3].y;
        s += u * u;
        u = (A[3].z < 0.f && B[3].z < 0.f) ? (B[3].z - 2.f * A[3].z) : B[3].z;
        s += u * u;
        u = (A[3].w < 0.f && B[3].w < 0.f) ? (B[3].w - 2.f * A[3].w) : B[3].w;
        s += u * u;
        acc3 += s;
    }
}

__global__ __launch_bounds__(256) void fdloss_kernel(
    const float4* __restrict__ src,   // b
    const float4* __restrict__ tgt,   // a
    int n4,
    int nchunk_total,
    int nchunk_full,
    float* __restrict__ out,
    double inv_n)
{
    const int t = threadIdx.x;

    float acc0 = 0.f, acc1 = 0.f, acc2 = 0.f, acc3 = 0.f;

    // Double-buffered chunk id: one bar.sync per chunk instead of two.
    __shared__ int s_chunk[2];
    if (t == 0) s_chunk[0] = (int)atomicAdd(&g_fdloss_work, 1u);
    __syncthreads();
    int p = 0;
    int chunk = s_chunk[0];

    while (chunk < nchunk_total) {
        // prefetch next chunk id into the other slot (no reader conflict:
        // slot p^1 was last read before the previous barrier)
        if (t == 0) s_chunk[p ^ 1] = (int)atomicAdd(&g_fdloss_work, 1u);

        const int base = chunk * CHUNK_F4;

        if (chunk < nchunk_full) {
            // two front-batched 8-load groups (each: MLP_p1 = 8)
            fd_group(src, tgt, base + t,        acc0, acc1, acc2, acc3);
            fd_group(src, tgt, base + t + 1024, acc0, acc1, acc2, acc3);
        } else {
            // partial tail chunk (n4 % CHUNK_F4 != 0): bounds-checked
            for (int i = base + t; i < n4; i += 256) {
                float4 b0 = src[i];
                float4 a0 = tgt[i];
                float u, s;
                u = (a0.x < 0.f && b0.x < 0.f) ? (b0.x - 2.f * a0.x) : b0.x;
                s = u * u;
                u = (a0.y < 0.f && b0.y < 0.f) ? (b0.y - 2.f * a0.y) : b0.y;
                s += u * u;
                u = (a0.z < 0.f && b0.z < 0.f) ? (b0.z - 2.f * a0.z) : b0.z;
                s += u * u;
                u = (a0.w < 0.f && b0.w < 0.f) ? (b0.w - 2.f * a0.w) : b0.w;
                s += u * u;
                acc0 += s;
            }
        }

        __syncthreads();  // orders t0's prefetch write before everyone's read
        p ^= 1;
        chunk = s_chunk[p];
    }

    // ---- per-block reduce (doubles only from here; off the streaming path)
    double acc = ((double)acc0 + (double)acc1) + ((double)acc2 + (double)acc3);

    #pragma unroll
    for (int off = 16; off > 0; off >>= 1)
        acc += __shfl_down_sync(0xFFFFFFFFu, acc, off);

    __shared__ double warp_sums[8];  // 256 threads = 8 warps
    const int lane = t & 31;
    const int wid  = t >> 5;
    if (lane == 0) warp_sums[wid] = acc;
    __syncthreads();

    __shared__ bool is_last;
    if (t == 0) {
        double v = warp_sums[0];
        #pragma unroll
        for (int w = 1; w < 8; w++) v += warp_sums[w];
        g_fdloss_partials[blockIdx.x] = v;   // uncontended STG (no atomic)
        __threadfence();                     // publish before ticket
        unsigned int ticket = atomicInc(&g_fdloss_tick, gridDim.x - 1u);
        is_last = (ticket == gridDim.x - 1u);
    }
    __syncthreads();

    if (is_last) {
        __threadfence();  // acquire: see all blocks' partial writes
        // parallel sum of gridDim.x partials across the whole block
        const volatile double* parts = g_fdloss_partials;
        double v = 0.0;
        for (int i = t; i < (int)gridDim.x; i += 256)
            v += parts[i];

        #pragma unroll
        for (int off = 16; off > 0; off >>= 1)
            v += __shfl_down_sync(0xFFFFFFFFu, v, off);

        __syncthreads();  // warp_sums reuse
        if (lane == 0) warp_sums[wid] = v;
        __syncthreads();

        if (t == 0) {
            double s = warp_sums[0];
            #pragma unroll
            for (int w = 1; w < 8; w++) s += warp_sums[w];
            out[0] = (float)(s * inv_n);
            atomicExch(&g_fdloss_work, 0u);  // restore state for next replay
        }
    }
}

extern "C" void kernel_launch(void* const* d_in, const int* in_sizes, int n_in,
                              void* d_out, int out_size) {
    const float* src = (const float*)d_in[0];  // source -> b
    const float* tgt = (const float*)d_in[1];  // target -> a
    float* out = (float*)d_out;

    const long long n = (long long)in_sizes[0];
    const int n4 = (int)(n / 4);   // n = 51,380,224 -> n4 = 12,845,056

    const int nchunk_full  = n4 / CHUNK_F4;                 // 6272 exact
    const int rem          = n4 - nchunk_full * CHUNK_F4;   // 0 for this shape
    const int nchunk_total = nchunk_full + (rem ? 1 : 0);

    const int threads = 256;
    // One resident wave: 148 SMs x 6 CTAs/SM (38 regs, 256 thr -> occ 6).
    int blocks = 148 * 6;
    if (blocks > nchunk_total) blocks = nchunk_total;
    if (blocks < 1) blocks = 1;
    if (blocks > 1024) blocks = 1024;  // g_fdloss_partials capacity

    fdloss_kernel<<<blocks, threads>>>(
        (const float4*)src, (const float4*)tgt, n4,
        nchunk_total, nchunk_full, out, 1.0 / (double)n);
}

// round 13
// speedup vs baseline: 1.0250x; 1.0250x over previous
#include <cuda_runtime.h>
#include <cuda_bf16.h>

// Scalar reduction: mean over all elements of
//   term = (a<0 && b<0) ? (b - 2a)^2 : b^2
// where a = target (d_in[1]), b = source (d_in[0]).
// Derivation: fdback - a = (a<0&&b<0) ? (b-a)-a = b-2a : (a-b)-a = -b.
//
// Single-kernel, self-resetting (graph-replay-safe) reduction with dynamic
// chunk scheduling. Chunk = 2048 float4 per array (32 KB/array): each thread
// processes 8 float4 per array as TWO front-batched groups of 8 LDG.128.
// Grid sized to EXACTLY one resident wave (148 SMs x 6 CTAs at 38 regs) so
// no straggler CTAs launch after the work queue drains. Per-block FP64
// atomicAdd epilogue overlaps the queue-drain window (measured faster than
// an uncontended-partials + last-block-gather epilogue).

__device__ double       g_fdloss_sum;    // zero-init at load; last block resets
__device__ unsigned int g_fdloss_tick;   // wrapping ticket; self-resets
__device__ unsigned int g_fdloss_work;   // chunk counter; last block resets

#define CHUNK_F4 2048   // float4 per chunk per array = 32 KB/array

// one front-batched group: 4 src + 4 tgt float4 at i0 + {0,256,512,768}
__device__ __forceinline__ void fd_group(
    const float4* __restrict__ src, const float4* __restrict__ tgt, int i0,
    float& acc0, float& acc1, float& acc2, float& acc3)
{
    float4 B[4], A[4];
    #pragma unroll
    for (int k = 0; k < 4; k++) {
        B[k] = src[i0 + k * 256];
        A[k] = tgt[i0 + k * 256];
    }
    {
        float u, s;
        u = (A[0].x < 0.f && B[0].x < 0.f) ? (B[0].x - 2.f * A[0].x) : B[0].x;
        s = u * u;
        u = (A[0].y < 0.f && B[0].y < 0.f) ? (B[0].y - 2.f * A[0].y) : B[0].y;
        s += u * u;
        u = (A[0].z < 0.f && B[0].z < 0.f) ? (B[0].z - 2.f * A[0].z) : B[0].z;
        s += u * u;
        u = (A[0].w < 0.f && B[0].w < 0.f) ? (B[0].w - 2.f * A[0].w) : B[0].w;
        s += u * u;
        acc0 += s;
    }
    {
        float u, s;
        u = (A[1].x < 0.f && B[1].x < 0.f) ? (B[1].x - 2.f * A[1].x) : B[1].x;
        s = u * u;
        u = (A[1].y < 0.f && B[1].y < 0.f) ? (B[1].y - 2.f * A[1].y) : B[1].y;
        s += u * u;
        u = (A[1].z < 0.f && B[1].z < 0.f) ? (B[1].z - 2.f * A[1].z) : B[1].z;
        s += u * u;
        u = (A[1].w < 0.f && B[1].w < 0.f) ? (B[1].w - 2.f * A[1].w) : B[1].w;
        s += u * u;
        acc1 += s;
    }
    {
        float u, s;
        u = (A[2].x < 0.f && B[2].x < 0.f) ? (B[2].x - 2.f * A[2].x) : B[2].x;
        s = u * u;
        u = (A[2].y < 0.f && B[2].y < 0.f) ? (B[2].y - 2.f * A[2].y) : B[2].y;
        s += u * u;
        u = (A[2].z < 0.f && B[2].z < 0.f) ? (B[2].z - 2.f * A[2].z) : B[2].z;
        s += u * u;
        u = (A[2].w < 0.f && B[2].w < 0.f) ? (B[2].w - 2.f * A[2].w) : B[2].w;
        s += u * u;
        acc2 += s;
    }
    {
        float u, s;
        u = (A[3].x < 0.f && B[3].x < 0.f) ? (B[3].x - 2.f * A[3].x) : B[3].x;
        s = u * u;
        u = (A[3].y < 0.f && B[3].y < 0.f) ? (B[3].y - 2.f * A[3].y) : B[3].y;
        s += u * u;
        u = (A[3].z < 0.f && B[3].z < 0.f) ? (B[3].z - 2.f * A[3].z) : B[3].z;
        s += u * u;
        u = (A[3].w < 0.f && B[3].w < 0.f) ? (B[3].w - 2.f * A[3].w) : B[3].w;
        s += u * u;
        acc3 += s;
    }
}

__global__ __launch_bounds__(256) void fdloss_kernel(
    const float4* __restrict__ src,   // b
    const float4* __restrict__ tgt,   // a
    int n4,
    int nchunk_total,
    int nchunk_full,
    float* __restrict__ out,
    double inv_n)
{
    const int t = threadIdx.x;

    float acc0 = 0.f, acc1 = 0.f, acc2 = 0.f, acc3 = 0.f;

    __shared__ int s_chunk;
    if (t == 0) s_chunk = (int)atomicAdd(&g_fdloss_work, 1u);
    __syncthreads();
    int chunk = s_chunk;

    while (chunk < nchunk_total) {
        __syncthreads();  // all threads captured s_chunk
        if (t == 0) s_chunk = (int)atomicAdd(&g_fdloss_work, 1u);  // prefetch

        const int base = chunk * CHUNK_F4;

        if (chunk < nchunk_full) {
            // two front-batched 8-load groups (each: MLP_p1 = 8)
            fd_group(src, tgt, base + t,        acc0, acc1, acc2, acc3);
            fd_group(src, tgt, base + t + 1024, acc0, acc1, acc2, acc3);
        } else {
            // partial tail chunk (n4 % CHUNK_F4 != 0): bounds-checked
            for (int i = base + t; i < n4; i += 256) {
                float4 b0 = src[i];
                float4 a0 = tgt[i];
                float u, s;
                u = (a0.x < 0.f && b0.x < 0.f) ? (b0.x - 2.f * a0.x) : b0.x;
                s = u * u;
                u = (a0.y < 0.f && b0.y < 0.f) ? (b0.y - 2.f * a0.y) : b0.y;
                s += u * u;
                u = (a0.z < 0.f && b0.z < 0.f) ? (b0.z - 2.f * a0.z) : b0.z;
                s += u * u;
                u = (a0.w < 0.f && b0.w < 0.f) ? (b0.w - 2.f * a0.w) : b0.w;
                s += u * u;
                acc0 += s;
            }
        }

        __syncthreads();  // prefetched s_chunk visible
        chunk = s_chunk;
    }

    // doubles only from here on (off the memory-paced path)
    double acc = ((double)acc0 + (double)acc1) + ((double)acc2 + (double)acc3);

    // warp reduce (double)
    #pragma unroll
    for (int off = 16; off > 0; off >>= 1)
        acc += __shfl_down_sync(0xFFFFFFFFu, acc, off);

    __shared__ double warp_sums[8];  // 256 threads = 8 warps
    const int lane = t & 31;
    const int wid  = t >> 5;
    if (lane == 0) warp_sums[wid] = acc;
    __syncthreads();

    __shared__ bool is_last;
    if (t == 0) {
        double v = warp_sums[0];
        #pragma unroll
        for (int w = 1; w < 8; w++) v += warp_sums[w];
        atomicAdd(&g_fdloss_sum, v);
        __threadfence();
        unsigned int ticket = atomicInc(&g_fdloss_tick, gridDim.x - 1u);
        is_last = (ticket == gridDim.x - 1u);
    }
    __syncthreads();

    if (is_last && t == 0) {
        __threadfence();
        double s = g_fdloss_sum;
        out[0] = (float)(s * inv_n);
        g_fdloss_sum = 0.0;              // restore state for next replay
        atomicExch(&g_fdloss_work, 0u);  // restore work counter
    }
}

extern "C" void kernel_launch(void* const* d_in, const int* in_sizes, int n_in,
                              void* d_out, int out_size) {
    const float* src = (const float*)d_in[0];  // source -> b
    const float* tgt = (const float*)d_in[1];  // target -> a
    float* out = (float*)d_out;

    const long long n = (long long)in_sizes[0];
    const int n4 = (int)(n / 4);   // n = 51,380,224 -> n4 = 12,845,056

    const int nchunk_full  = n4 / CHUNK_F4;                 // 6272 exact
    const int rem          = n4 - nchunk_full * CHUNK_F4;   // 0 for this shape
    const int nchunk_total = nchunk_full + (rem ? 1 : 0);

    const int threads = 256;
    // One resident wave: 148 SMs x 6 CTAs/SM (38 regs, 256 thr -> occ 6).
    int blocks = 148 * 6;
    if (blocks > nchunk_total) blocks = nchunk_total;
    if (blocks < 1) blocks = 1;

    fdloss_kernel<<<blocks, threads>>>(
        (const float4*)src, (const float4*)tgt, n4,
        nchunk_total, nchunk_full, out, 1.0 / (double)n);
}

// round 14
// speedup vs baseline: 1.0281x; 1.0030x over previous
#include <cuda_runtime.h>
#include <cuda_bf16.h>

// Scalar reduction: mean over all elements of
//   term = (a<0 && b<0) ? (b - 2a)^2 : b^2
// where a = target (d_in[1]), b = source (d_in[0]).
// Derivation: fdback - a = (a<0&&b<0) ? (b-a)-a = b-2a : (a-b)-a = -b.
//
// Single-kernel, self-resetting (graph-replay-safe) reduction with dynamic
// chunk scheduling (CHUNK=2048 float4/array; dual front-batched 8-load
// groups; one-wave grid 888 = 148x6). Loads use the L2::256B prefetch hint:
// each miss pulls the aligned 256B line-pair, halving independent DRAM
// transactions on this perfectly sequential dense stream.

__device__ double       g_fdloss_sum;    // zero-init at load; last block resets
__device__ unsigned int g_fdloss_tick;   // wrapping ticket; self-resets
__device__ unsigned int g_fdloss_work;   // chunk counter; last block resets

#define CHUNK_F4 2048   // float4 per chunk per array = 32 KB/array

// 128-bit load with 256B L2 prefetch hint (dense sequential stream: the
// sibling 128B line is always consumed, so the wider fetch is free win).
__device__ __forceinline__ float4 ldg_256b(const float4* __restrict__ p) {
    float4 v;
    asm volatile("ld.global.nc.L2::256B.v4.f32 {%0,%1,%2,%3}, [%4];"
                 : "=f"(v.x), "=f"(v.y), "=f"(v.z), "=f"(v.w)
                 : "l"(p));
    return v;
}

// one front-batched group: 4 src + 4 tgt float4 at i0 + {0,256,512,768}
__device__ __forceinline__ void fd_group(
    const float4* __restrict__ src, const float4* __restrict__ tgt, int i0,
    float& acc0, float& acc1, float& acc2, float& acc3)
{
    float4 B[4], A[4];
    #pragma unroll
    for (int k = 0; k < 4; k++) {
        B[k] = ldg_256b(src + i0 + k * 256);
        A[k] = ldg_256b(tgt + i0 + k * 256);
    }
    {
        float u, s;
        u = (A[0].x < 0.f && B[0].x < 0.f) ? (B[0].x - 2.f * A[0].x) : B[0].x;
        s = u * u;
        u = (A[0].y < 0.f && B[0].y < 0.f) ? (B[0].y - 2.f * A[0].y) : B[0].y;
        s += u * u;
        u = (A[0].z < 0.f && B[0].z < 0.f) ? (B[0].z - 2.f * A[0].z) : B[0].z;
        s += u * u;
        u = (A[0].w < 0.f && B[0].w < 0.f) ? (B[0].w - 2.f * A[0].w) : B[0].w;
        s += u * u;
        acc0 += s;
    }
    {
        float u, s;
        u = (A[1].x < 0.f && B[1].x < 0.f) ? (B[1].x - 2.f * A[1].x) : B[1].x;
        s = u * u;
        u = (A[1].y < 0.f && B[1].y < 0.f) ? (B[1].y - 2.f * A[1].y) : B[1].y;
        s += u * u;
        u = (A[1].z < 0.f && B[1].z < 0.f) ? (B[1].z - 2.f * A[1].z) : B[1].z;
        s += u * u;
        u = (A[1].w < 0.f && B[1].w < 0.f) ? (B[1].w - 2.f * A[1].w) : B[1].w;
        s += u * u;
        acc1 += s;
    }
    {
        float u, s;
        u = (A[2].x < 0.f && B[2].x < 0.f) ? (B[2].x - 2.f * A[2].x) : B[2].x;
        s = u * u;
        u = (A[2].y < 0.f && B[2].y < 0.f) ? (B[2].y - 2.f * A[2].y) : B[2].y;
        s += u * u;
        u = (A[2].z < 0.f && B[2].z < 0.f) ? (B[2].z - 2.f * A[2].z) : B[2].z;
        s += u * u;
        u = (A[2].w < 0.f && B[2].w < 0.f) ? (B[2].w - 2.f * A[2].w) : B[2].w;
        s += u * u;
        acc2 += s;
    }
    {
        float u, s;
        u = (A[3].x < 0.f && B[3].x < 0.f) ? (B[3].x - 2.f * A[3].x) : B[3].x;
        s = u * u;
        u = (A[3].y < 0.f && B[3].y < 0.f) ? (B[3].y - 2.f * A[3].y) : B[3].y;
        s += u * u;
        u = (A[3].z < 0.f && B[3].z < 0.f) ? (B[3].z - 2.f * A[3].z) : B[3].z;
        s += u * u;
        u = (A[3].w < 0.f && B[3].w < 0.f) ? (B[3].w - 2.f * A[3].w) : B[3].w;
        s += u * u;
        acc3 += s;
    }
}

__global__ __launch_bounds__(256) void fdloss_kernel(
    const float4* __restrict__ src,   // b
    const float4* __restrict__ tgt,   // a
    int n4,
    int nchunk_total,
    int nchunk_full,
    float* __restrict__ out,
    double inv_n)
{
    const int t = threadIdx.x;

    float acc0 = 0.f, acc1 = 0.f, acc2 = 0.f, acc3 = 0.f;

    __shared__ int s_chunk;
    if (t == 0) s_chunk = (int)atomicAdd(&g_fdloss_work, 1u);
    __syncthreads();
    int chunk = s_chunk;

    while (chunk < nchunk_total) {
        __syncthreads();  // all threads captured s_chunk
        if (t == 0) s_chunk = (int)atomicAdd(&g_fdloss_work, 1u);  // prefetch

        const int base = chunk * CHUNK_F4;

        if (chunk < nchunk_full) {
            // two front-batched 8-load groups (each: MLP_p1 = 8)
            fd_group(src, tgt, base + t,        acc0, acc1, acc2, acc3);
            fd_group(src, tgt, base + t + 1024, acc0, acc1, acc2, acc3);
        } else {
            // partial tail chunk (n4 % CHUNK_F4 != 0): bounds-checked
            for (int i = base + t; i < n4; i += 256) {
                float4 b0 = src[i];
                float4 a0 = tgt[i];
                float u, s;
                u = (a0.x < 0.f && b0.x < 0.f) ? (b0.x - 2.f * a0.x) : b0.x;
                s = u * u;
                u = (a0.y < 0.f && b0.y < 0.f) ? (b0.y - 2.f * a0.y) : b0.y;
                s += u * u;
                u = (a0.z < 0.f && b0.z < 0.f) ? (b0.z - 2.f * a0.z) : b0.z;
                s += u * u;
                u = (a0.w < 0.f && b0.w < 0.f) ? (b0.w - 2.f * a0.w) : b0.w;
                s += u * u;
                acc0 += s;
            }
        }

        __syncthreads();  // prefetched s_chunk visible
        chunk = s_chunk;
    }

    // doubles only from here on (off the memory-paced path)
    double acc = ((double)acc0 + (double)acc1) + ((double)acc2 + (double)acc3);

    // warp reduce (double)
    #pragma unroll
    for (int off = 16; off > 0; off >>= 1)
        acc += __shfl_down_sync(0xFFFFFFFFu, acc, off);

    __shared__ double warp_sums[8];  // 256 threads = 8 warps
    const int lane = t & 31;
    const int wid  = t >> 5;
    if (lane == 0) warp_sums[wid] = acc;
    __syncthreads();

    __shared__ bool is_last;
    if (t == 0) {
        double v = warp_sums[0];
        #pragma unroll
        for (int w = 1; w < 8; w++) v += warp_sums[w];
        atomicAdd(&g_fdloss_sum, v);
        __threadfence();
        unsigned int ticket = atomicInc(&g_fdloss_tick, gridDim.x - 1u);
        is_last = (ticket == gridDim.x - 1u);
    }
    __syncthreads();

    if (is_last && t == 0) {
        __threadfence();
        double s = g_fdloss_sum;
        out[0] = (float)(s * inv_n);
        g_fdloss_sum = 0.0;              // restore state for next replay
        atomicExch(&g_fdloss_work, 0u);  // restore work counter
    }
}

extern "C" void kernel_launch(void* const* d_in, const int* in_sizes, int n_in,
                              void* d_out, int out_size) {
    const float* src = (const float*)d_in[0];  // source -> b
    const float* tgt = (const float*)d_in[1];  // target -> a
    float* out = (float*)d_out;

    const long long n = (long long)in_sizes[0];
    const int n4 = (int)(n / 4);   // n = 51,380,224 -> n4 = 12,845,056

    const int nchunk_full  = n4 / CHUNK_F4;                 // 6272 exact
    const int rem          = n4 - nchunk_full * CHUNK_F4;   // 0 for this shape
    const int nchunk_total = nchunk_full + (rem ? 1 : 0);

    const int threads = 256;
    // One resident wave: 148 SMs x 6 CTAs/SM (38 regs, 256 thr -> occ 6).
    int blocks = 148 * 6;
    if (blocks > nchunk_total) blocks = nchunk_total;
    if (blocks < 1) blocks = 1;

    fdloss_kernel<<<blocks, threads>>>(
        (const float4*)src, (const float4*)tgt, n4,
        nchunk_total, nchunk_full, out, 1.0 / (double)n);
}